// round 13
// baseline (speedup 1.0000x reference)
#include <cuda_runtime.h>
#include <cuda_fp16.h>
#include <cstdint>

// Problem constants
#define B  2
#define L  8192
#define D  1024
#define NFFT 16384
#define TPB 1024
#define NTW (NFFT / 4)                        // 4096 twiddles = 32 KB
#define NPAD (NFFT + NFFT/16)
#define SMEM_CONVH (NPAD * sizeof(float2) + NFFT * sizeof(__half2))  // 139264 + 65536 = 204800

// ---------------- device scratch ----------------
__device__ __half  g_xt[(size_t)B * D * L];   // x transposed [B][D][L], fp16
__device__ __half  g_hth[(size_t)D * L];      // h transposed [D][L], fp16
__device__ __half  g_yt[(size_t)B * D * L];   // y transposed [B][D][L], fp16
__device__ float2  g_tw[NTW];

// ---------------- helpers ----------------
__device__ __forceinline__ int pidx(int a) { return a + (a >> 4); }

__device__ __forceinline__ float2 cmul(float2 a, float2 b) {
    return make_float2(fmaf(a.x, b.x, -a.y * b.y),
                       fmaf(a.x, b.y,  a.y * b.x));
}
__device__ __forceinline__ float2 cadd(float2 a, float2 b) { return make_float2(a.x + b.x, a.y + b.y); }
__device__ __forceinline__ float2 csub(float2 a, float2 b) { return make_float2(a.x - b.x, a.y - b.y); }

__device__ __forceinline__ void bf4_dif(float2& a0, float2& a1, float2& a2, float2& a3) {
    float2 t0 = cadd(a0, a2), t1 = csub(a0, a2);
    float2 t2 = cadd(a1, a3), t3 = csub(a1, a3);
    a0 = cadd(t0, t2);
    a2 = csub(t0, t2);
    a1 = make_float2(t1.x + t3.y, t1.y - t3.x);  // t1 - i*t3
    a3 = make_float2(t1.x - t3.y, t1.y + t3.x);  // t1 + i*t3
}
__device__ __forceinline__ void bf4_dit(float2& a0, float2& a1, float2& a2, float2& a3) {
    float2 t0 = cadd(a0, a2), t1 = csub(a0, a2);
    float2 t2 = cadd(a1, a3), t3 = csub(a1, a3);
    a0 = cadd(t0, t2);
    a2 = csub(t0, t2);
    a1 = make_float2(t1.x - t3.y, t1.y + t3.x);  // t1 + i*t3
    a3 = make_float2(t1.x + t3.y, t1.y - t3.x);  // t1 - i*t3
}

// base-4 digit reversal of 14 bits: bit-reverse then swap adjacent bit pairs
__device__ __forceinline__ int rev4_14(int x) {
    unsigned y = __brev((unsigned)x) >> 18;
    return (int)(((y & 0x2AAAu) >> 1) | ((y & 0x1555u) << 1));
}
__device__ __forceinline__ int qperm(int p) {
    return rev4_14((NFFT - rev4_14(p)) & (NFFT - 1));
}

// ---------------- init: twiddles ----------------
__global__ void init_kernel() {
    int k = blockIdx.x * blockDim.x + threadIdx.x;
    if (k < NTW) {
        float s, c;
        sincospif(-2.0f * (float)k / (float)NFFT, &s, &c);
        g_tw[k] = make_float2(c, s);
    }
}

#define TTW 132   // padded tile row width in floats (128 + 4)

// ---------------- fp32 -> fp16 transpose: in[R][C] f32 -> out[C][R] f16 ----------------
__global__ void transpose_f32f16_kernel(const float* __restrict__ in, __half* __restrict__ out,
                                        int R, int C) {
    __shared__ float t[32 * TTW];
    const size_t zoff = (size_t)blockIdx.z * (size_t)R * (size_t)C;
    const int cbase = blockIdx.x * 128;
    const int rbase = blockIdx.y * 32;
    const int x = threadIdx.x, y = threadIdx.y;

    const float4* __restrict__ in4 = (const float4*)(in + zoff);
#pragma unroll
    for (int it = 0; it < 4; it++) {
        const int r = y + 8 * it;
        float4 v = in4[((size_t)(rbase + r) * C + cbase) / 4 + x];
        *(float4*)&t[r * TTW + 4 * x] = v;
    }
    __syncthreads();

    __half* __restrict__ outz = out + zoff;
#pragma unroll
    for (int it = 0; it < 4; it++) {
        const int c_loc = x + 32 * it;
        __half2 h01 = __floats2half2_rn(t[(4 * y + 0) * TTW + c_loc],
                                        t[(4 * y + 1) * TTW + c_loc]);
        __half2 h23 = __floats2half2_rn(t[(4 * y + 2) * TTW + c_loc],
                                        t[(4 * y + 3) * TTW + c_loc]);
        uint2 packed = make_uint2(*(const unsigned*)&h01, *(const unsigned*)&h23);
        *(uint2*)&outz[(size_t)(cbase + c_loc) * R + rbase + 4 * y] = packed;
    }
}

// ---------------- fp16 -> fp32 transpose: in[R][C] f16 -> out[C][R] f32 (y path) ----
__global__ void transpose_f16f32_kernel(const __half* __restrict__ in, float* __restrict__ out,
                                        int R, int C) {
    __shared__ float t[32 * TTW];
    const size_t zoff = (size_t)blockIdx.z * (size_t)R * (size_t)C;
    const int cbase = blockIdx.x * 128;
    const int rbase = blockIdx.y * 32;
    const int x = threadIdx.x, y = threadIdx.y;

    const __half* __restrict__ inz = in + zoff;
#pragma unroll
    for (int it = 0; it < 4; it++) {
        const int r = y + 8 * it;
        uint2 raw = *(const uint2*)&inz[(size_t)(rbase + r) * C + cbase + 4 * x];
        float2 f01 = __half22float2(*(const __half2*)&raw.x);
        float2 f23 = __half22float2(*(const __half2*)&raw.y);
        *(float4*)&t[r * TTW + 4 * x] = make_float4(f01.x, f01.y, f23.x, f23.y);
    }
    __syncthreads();

    float* __restrict__ outz = out + zoff;
#pragma unroll
    for (int it = 0; it < 4; it++) {
        const int c_loc = x + 32 * it;
        float4 v;
        v.x = t[(4 * y + 0) * TTW + c_loc];
        v.y = t[(4 * y + 1) * TTW + c_loc];
        v.z = t[(4 * y + 2) * TTW + c_loc];
        v.w = t[(4 * y + 3) * TTW + c_loc];
        *(float4*)&outz[(size_t)(cbase + c_loc) * R + rbase + 4 * y] = v;
    }
}

// ---------------- fused first fwd stage (14+12), fp16 rows, zero upper half ----------
// NOTE: caller must __syncthreads() before this (it writes sd with no leading barrier).
__device__ __forceinline__ void stageA_fwd_f16(const __half* __restrict__ row0,
                                               const __half* __restrict__ row1,
                                               float2* sd, int tid) {
    float2 v[4][4];
    const int pb = tid + (tid >> 4);
#pragma unroll
    for (int r = 0; r < 4; r++) {
        const int i0 = tid + r * 1024;
        const int i1 = i0 + 4096;
        float2 a0 = make_float2(__half2float(row0[i0]), __half2float(row1[i0]));
        float2 a1 = make_float2(__half2float(row0[i1]), __half2float(row1[i1]));
        float2 X0 = cadd(a0, a1);
        float2 X2 = csub(a0, a1);
        float2 X1 = make_float2(a0.x + a1.y, a0.y - a1.x);
        float2 X3 = make_float2(a0.x - a1.y, a0.y + a1.x);
        float2 w  = g_tw[tid + r * 1024];
        float2 w2 = cmul(w, w);
        float2 w3 = cmul(w2, w);
        v[r][0] = X0;
        v[r][1] = cmul(X1, w);
        v[r][2] = cmul(X2, w2);
        v[r][3] = cmul(X3, w3);
    }
    {
        float2 wb  = g_tw[4 * tid];
        float2 wb2 = cmul(wb, wb);
        float2 wb3 = cmul(wb2, wb);
#pragma unroll
        for (int s = 0; s < 4; s++) {
            bf4_dif(v[0][s], v[1][s], v[2][s], v[3][s]);
            v[1][s] = cmul(v[1][s], wb);
            v[2][s] = cmul(v[2][s], wb2);
            v[3][s] = cmul(v[3][s], wb3);
        }
    }
#pragma unroll
    for (int r = 0; r < 4; r++)
#pragma unroll
        for (int s = 0; s < 4; s++) {
            const int off = r * 1024 + s * 4096;
            sd[pb + off + (off >> 4)] = v[r][s];
        }
}

// ---------------- combined DIF stages (LS, LS-2), smem in/out ----------------
template<int LS>
__device__ __forceinline__ void dif_pair(float2* sd, int tid) {
    constexpr int Q2 = 1 << (LS - 4);
    constexpr int Q  = 1 << (LS - 2);
    constexpr int S  = 1 << (14 - LS);
    __syncthreads();
    const int j2 = tid & (Q2 - 1);
    const int g  = tid >> (LS - 4);
    const int base = (g << LS) + j2;
    const int pb = base + (base >> 4);
    float2 v[4][4];
#pragma unroll
    for (int r = 0; r < 4; r++)
#pragma unroll
        for (int s = 0; s < 4; s++) {
            const int off = r * Q2 + s * Q;
            v[r][s] = sd[pb + off + (off >> 4)];
        }
#pragma unroll
    for (int r = 0; r < 4; r++) {
        bf4_dif(v[r][0], v[r][1], v[r][2], v[r][3]);
        float2 w  = g_tw[(j2 + r * Q2) * S];
        float2 w2 = cmul(w, w);
        float2 w3 = cmul(w2, w);
        v[r][1] = cmul(v[r][1], w);
        v[r][2] = cmul(v[r][2], w2);
        v[r][3] = cmul(v[r][3], w3);
    }
    {
        float2 wb  = g_tw[j2 * (4 * S)];
        float2 wb2 = cmul(wb, wb);
        float2 wb3 = cmul(wb2, wb);
#pragma unroll
        for (int s = 0; s < 4; s++) {
            bf4_dif(v[0][s], v[1][s], v[2][s], v[3][s]);
            v[1][s] = cmul(v[1][s], wb);
            v[2][s] = cmul(v[2][s], wb2);
            v[3][s] = cmul(v[3][s], wb3);
        }
    }
#pragma unroll
    for (int r = 0; r < 4; r++)
#pragma unroll
        for (int s = 0; s < 4; s++) {
            const int off = r * Q2 + s * Q;
            sd[pb + off + (off >> 4)] = v[r][s];
        }
}

// final DIF stage ls=2, sd in/out
__device__ __forceinline__ void dif_last(float2* sd, int tid) {
    __syncthreads();
#pragma unroll
    for (int tt = 0; tt < (NFFT / 4) / TPB; ++tt) {
        int t = tid + tt * TPB;
        int pb = 4 * t + (t >> 2);
        float2 a0 = sd[pb + 0];
        float2 a1 = sd[pb + 1];
        float2 a2 = sd[pb + 2];
        float2 a3 = sd[pb + 3];
        bf4_dif(a0, a1, a2, a3);
        sd[pb + 0] = a0;
        sd[pb + 1] = a1;
        sd[pb + 2] = a2;
        sd[pb + 3] = a3;
    }
}

// final DIF stage ls=2, sd in -> zh (fp16 packed spectrum) out
__device__ __forceinline__ void dif_last_to_zh(float2* sd, __half2* zh, int tid) {
    __syncthreads();
#pragma unroll
    for (int tt = 0; tt < (NFFT / 4) / TPB; ++tt) {
        int t = tid + tt * TPB;
        int pb = 4 * t + (t >> 2);
        float2 a0 = sd[pb + 0];
        float2 a1 = sd[pb + 1];
        float2 a2 = sd[pb + 2];
        float2 a3 = sd[pb + 3];
        bf4_dif(a0, a1, a2, a3);
        zh[4 * t + 0] = __floats2half2_rn(a0.x, a0.y);
        zh[4 * t + 1] = __floats2half2_rn(a1.x, a1.y);
        zh[4 * t + 2] = __floats2half2_rn(a2.x, a2.y);
        zh[4 * t + 3] = __floats2half2_rn(a3.x, a3.y);
    }
}

// first DIT stage ls=2
__device__ __forceinline__ void dit_first(float2* sd, int tid) {
    __syncthreads();
#pragma unroll
    for (int tt = 0; tt < (NFFT / 4) / TPB; ++tt) {
        int t = tid + tt * TPB;
        int pb = 4 * t + (t >> 2);
        float2 a0 = sd[pb + 0];
        float2 a1 = sd[pb + 1];
        float2 a2 = sd[pb + 2];
        float2 a3 = sd[pb + 3];
        bf4_dit(a0, a1, a2, a3);
        sd[pb + 0] = a0;
        sd[pb + 1] = a1;
        sd[pb + 2] = a2;
        sd[pb + 3] = a3;
    }
}

// combined DIT stages (LSA, LSA+2), smem in/out
template<int LSA>
__device__ __forceinline__ void dit_pair(float2* sd, int tid) {
    constexpr int QA   = 1 << (LSA - 2);
    constexpr int SA   = 1 << (14 - LSA);
    constexpr int QB   = 1 << LSA;
    constexpr int SB   = SA >> 2;
    constexpr int LENB = 1 << (LSA + 2);
    __syncthreads();
    const int j = tid & (QA - 1);
    const int G = tid >> (LSA - 2);
    const int base = G * LENB + j;
    const int pb = base + (base >> 4);
    float2 v[4][4];
#pragma unroll
    for (int r = 0; r < 4; r++)
#pragma unroll
        for (int s = 0; s < 4; s++) {
            const int off = r * QA + s * QB;
            v[r][s] = sd[pb + off + (off >> 4)];
        }
    {
        float2 w   = g_tw[j * SA];
        float2 wc  = make_float2(w.x, -w.y);
        float2 wc2 = cmul(wc, wc);
        float2 wc3 = cmul(wc2, wc);
#pragma unroll
        for (int s = 0; s < 4; s++) {
            v[1][s] = cmul(v[1][s], wc);
            v[2][s] = cmul(v[2][s], wc2);
            v[3][s] = cmul(v[3][s], wc3);
            bf4_dit(v[0][s], v[1][s], v[2][s], v[3][s]);
        }
    }
#pragma unroll
    for (int r = 0; r < 4; r++) {
        float2 w   = g_tw[(j + r * QA) * SB];
        float2 wc  = make_float2(w.x, -w.y);
        float2 wc2 = cmul(wc, wc);
        float2 wc3 = cmul(wc2, wc);
        v[r][1] = cmul(v[r][1], wc);
        v[r][2] = cmul(v[r][2], wc2);
        v[r][3] = cmul(v[r][3], wc3);
        bf4_dit(v[r][0], v[r][1], v[r][2], v[r][3]);
    }
#pragma unroll
    for (int r = 0; r < 4; r++)
#pragma unroll
        for (int s = 0; s < 4; s++) {
            const int off = r * QA + s * QB;
            sd[pb + off + (off >> 4)] = v[r][s];
        }
}

// ---------------- fused conv+hfft: 2 channels x 2 batches per block ----------------
__global__ __launch_bounds__(TPB, 1)
void convh_kernel(const float* __restrict__ bias) {
    extern __shared__ char smraw[];
    float2*  sd = (float2*)smraw;
    __half2* zh = (__half2*)(smraw + NPAD * sizeof(float2));
    const int tid = threadIdx.x;
    const int d0  = 2 * blockIdx.x;
    const int d1  = d0 + 1;

    // ---- H spectrum: FFT(h_d0 + i*h_d1) -> zh (fp16 packed, digit-reversed) ----
    stageA_fwd_f16(g_hth + (size_t)d0 * L, g_hth + (size_t)d1 * L, sd, tid);
    dif_pair<10>(sd, tid);
    dif_pair<6>(sd, tid);
    dif_last_to_zh(sd, zh, tid);

    const float invN = 1.0f / (float)NFFT;
    const float bd0 = bias[d0];
    const float bd1 = bias[d1];

    // ---- per batch: FFT(x) -> pair multiply -> IFFT -> y ----
#pragma unroll 1
    for (int b = 0; b < 2; b++) {
        const __half* __restrict__ xr0 = g_xt + ((size_t)b * D + d0) * L;
        const __half* __restrict__ xr1 = g_xt + ((size_t)b * D + d1) * L;

        __syncthreads();                      // prior pass's sd reads must finish
        stageA_fwd_f16(xr0, xr1, sd, tid);
        dif_pair<10>(sd, tid);
        dif_pair<6>(sd, tid);
        dif_last(sd, tid);

        // pair-ownership multiply: split X and H, multiply per channel, recombine.
        __syncthreads();
#pragma unroll
        for (int tt = 0; tt < NFFT / TPB; ++tt) {
            int p = tid + tt * TPB;
            int q = qperm(p);
            if (p > q) continue;
            float2 Zp = sd[p + (p >> 4)];
            float2 Zq = sd[q + (q >> 4)];
            float2 Hp = __half22float2(zh[p]);
            float2 Hq = __half22float2(zh[q]);
            // Hermitian splits (packed a+ib of two real signals)
            float2 X0 = make_float2(0.5f * (Zp.x + Zq.x), 0.5f * (Zp.y - Zq.y));
            float2 X1 = make_float2(0.5f * (Zp.y + Zq.y), 0.5f * (Zq.x - Zp.x));
            float2 H0 = make_float2(0.5f * (Hp.x + Hq.x), 0.5f * (Hp.y - Hq.y));
            float2 H1 = make_float2(0.5f * (Hp.y + Hq.y), 0.5f * (Hq.x - Hp.x));
            float2 Y0 = cmul(X0, H0);
            float2 Y1 = cmul(X1, H1);
            // repack: W = Y0 + i*Y1 at p; conj-partner at q
            sd[p + (p >> 4)] = make_float2(Y0.x - Y1.y, Y0.y + Y1.x);
            sd[q + (q >> 4)] = make_float2(Y0.x + Y1.y, Y1.x - Y0.y);
        }

        dit_first(sd, tid);
        dit_pair<4>(sd, tid);
        dit_pair<8>(sd, tid);

        // fused final inverse stage (12+14): smem -> regs -> gmem fp16 (idx < L only)
        __syncthreads();
        {
            const int pb = tid + (tid >> 4);
            float2 v[4][4];
#pragma unroll
            for (int r = 0; r < 4; r++)
#pragma unroll
                for (int s = 0; s < 4; s++) {
                    const int off = r * 1024 + s * 4096;
                    v[r][s] = sd[pb + off + (off >> 4)];
                }
            {
                float2 w   = g_tw[4 * tid];
                float2 wc  = make_float2(w.x, -w.y);
                float2 wc2 = cmul(wc, wc);
                float2 wc3 = cmul(wc2, wc);
#pragma unroll
                for (int s = 0; s < 4; s++) {
                    v[1][s] = cmul(v[1][s], wc);
                    v[2][s] = cmul(v[2][s], wc2);
                    v[3][s] = cmul(v[3][s], wc3);
                    bf4_dit(v[0][s], v[1][s], v[2][s], v[3][s]);
                }
            }
            __half* __restrict__ y0 = g_yt + ((size_t)b * D + d0) * L;
            __half* __restrict__ y1 = g_yt + ((size_t)b * D + d1) * L;
#pragma unroll
            for (int r = 0; r < 4; r++) {
                float2 w   = g_tw[tid + r * 1024];
                float2 wc  = make_float2(w.x, -w.y);
                float2 wc2 = cmul(wc, wc);
                float2 wc3 = cmul(wc2, wc);
                v[r][1] = cmul(v[r][1], wc);
                v[r][2] = cmul(v[r][2], wc2);
                v[r][3] = cmul(v[r][3], wc3);
                bf4_dit(v[r][0], v[r][1], v[r][2], v[r][3]);
#pragma unroll
                for (int s = 0; s < 2; s++) {
                    const int idx = tid + r * 1024 + s * 4096;
                    y0[idx] = __float2half_rn(fmaf(v[r][s].x, invN, bd0));
                    y1[idx] = __float2half_rn(fmaf(v[r][s].y, invN, bd1));
                }
            }
        }
    }
}

// ---------------- launch ----------------
extern "C" void kernel_launch(void* const* d_in, const int* in_sizes, int n_in,
                              void* d_out, int out_size) {
    const float* x    = (const float*)d_in[0];
    const float* h    = (const float*)d_in[1];
    const float* bias = (const float*)d_in[2];
    float* out = (float*)d_out;

    void *xt_p, *hth_p, *yt_p;
    cudaGetSymbolAddress(&xt_p,  g_xt);
    cudaGetSymbolAddress(&hth_p, g_hth);
    cudaGetSymbolAddress(&yt_p,  g_yt);

    cudaFuncSetAttribute(convh_kernel, cudaFuncAttributeMaxDynamicSharedMemorySize, SMEM_CONVH);

    init_kernel<<<8, 512>>>();
    // x: [L][D] fp32 per batch -> [D][L] fp16
    transpose_f32f16_kernel<<<dim3(D / 128, L / 32, B), dim3(32, 8)>>>(x, (__half*)xt_p, L, D);
    // h: [L][D] fp32 -> [D][L] fp16
    transpose_f32f16_kernel<<<dim3(D / 128, L / 32, 1), dim3(32, 8)>>>(h, (__half*)hth_p, L, D);
    // fused hfft+conv: 512 blocks, 2 channels x 2 batches each
    convh_kernel<<<D / 2, TPB, SMEM_CONVH>>>(bias);
    // y: [D][L] fp16 per batch -> [L][D] fp32
    transpose_f16f32_kernel<<<dim3(L / 128, D / 32, B), dim3(32, 8)>>>((const __half*)yt_p, out, D, L);
}

// round 14
// speedup vs baseline: 1.0324x; 1.0324x over previous
#include <cuda_runtime.h>
#include <cuda_fp16.h>
#include <cstdint>

// Problem constants
#define B  2
#define L  8192
#define D  1024
#define NFFT 16384
#define TPB 1024
#define NTW (NFFT / 4)                        // 4096 twiddles = 32 KB
#define NPAD (NFFT + NFFT/16)
#define SMEM_CONVH (NPAD * sizeof(float2) + NFFT * sizeof(__half2))  // 204800 B

// ---------------- device scratch ----------------
__device__ __half  g_xt[(size_t)B * D * L];   // x transposed [B][D][L], fp16
__device__ __half  g_hth[(size_t)D * L];      // h transposed [D][L], fp16
__device__ __half  g_yt[(size_t)B * D * L];   // y transposed [B][D][L], fp16
__device__ float2  g_tw[NTW];

// ---------------- helpers ----------------
__device__ __forceinline__ int pidx(int a) { return a + (a >> 4); }

__device__ __forceinline__ float2 cmul(float2 a, float2 b) {
    return make_float2(fmaf(a.x, b.x, -a.y * b.y),
                       fmaf(a.x, b.y,  a.y * b.x));
}
__device__ __forceinline__ float2 cadd(float2 a, float2 b) { return make_float2(a.x + b.x, a.y + b.y); }
__device__ __forceinline__ float2 csub(float2 a, float2 b) { return make_float2(a.x - b.x, a.y - b.y); }

__device__ __forceinline__ void bf4_dif(float2& a0, float2& a1, float2& a2, float2& a3) {
    float2 t0 = cadd(a0, a2), t1 = csub(a0, a2);
    float2 t2 = cadd(a1, a3), t3 = csub(a1, a3);
    a0 = cadd(t0, t2);
    a2 = csub(t0, t2);
    a1 = make_float2(t1.x + t3.y, t1.y - t3.x);  // t1 - i*t3
    a3 = make_float2(t1.x - t3.y, t1.y + t3.x);  // t1 + i*t3
}
__device__ __forceinline__ void bf4_dit(float2& a0, float2& a1, float2& a2, float2& a3) {
    float2 t0 = cadd(a0, a2), t1 = csub(a0, a2);
    float2 t2 = cadd(a1, a3), t3 = csub(a1, a3);
    a0 = cadd(t0, t2);
    a2 = csub(t0, t2);
    a1 = make_float2(t1.x - t3.y, t1.y + t3.x);  // t1 + i*t3
    a3 = make_float2(t1.x + t3.y, t1.y - t3.x);  // t1 - i*t3
}

// base-4 digit reversal of 14 bits: bit-reverse then swap adjacent bit pairs
__device__ __forceinline__ int rev4_14(int x) {
    unsigned y = __brev((unsigned)x) >> 18;
    return (int)(((y & 0x2AAAu) >> 1) | ((y & 0x1555u) << 1));
}
__device__ __forceinline__ int qperm(int p) {
    return rev4_14((NFFT - rev4_14(p)) & (NFFT - 1));
}

// ---------------- init: twiddles ----------------
__global__ void init_kernel() {
    int k = blockIdx.x * blockDim.x + threadIdx.x;
    if (k < NTW) {
        float s, c;
        sincospif(-2.0f * (float)k / (float)NFFT, &s, &c);
        g_tw[k] = make_float2(c, s);
    }
}

#define TTW 132   // padded tile row width in floats (128 + 4)

// ---------------- fp32 -> fp16 transpose: in[R][C] f32 -> out[C][R] f16 ----------------
__global__ void transpose_f32f16_kernel(const float* __restrict__ in, __half* __restrict__ out,
                                        int R, int C) {
    __shared__ float t[32 * TTW];
    const size_t zoff = (size_t)blockIdx.z * (size_t)R * (size_t)C;
    const int cbase = blockIdx.x * 128;
    const int rbase = blockIdx.y * 32;
    const int x = threadIdx.x, y = threadIdx.y;

    const float4* __restrict__ in4 = (const float4*)(in + zoff);
#pragma unroll
    for (int it = 0; it < 4; it++) {
        const int r = y + 8 * it;
        float4 v = in4[((size_t)(rbase + r) * C + cbase) / 4 + x];
        *(float4*)&t[r * TTW + 4 * x] = v;
    }
    __syncthreads();

    __half* __restrict__ outz = out + zoff;
#pragma unroll
    for (int it = 0; it < 4; it++) {
        const int c_loc = x + 32 * it;
        __half2 h01 = __floats2half2_rn(t[(4 * y + 0) * TTW + c_loc],
                                        t[(4 * y + 1) * TTW + c_loc]);
        __half2 h23 = __floats2half2_rn(t[(4 * y + 2) * TTW + c_loc],
                                        t[(4 * y + 3) * TTW + c_loc]);
        uint2 packed = make_uint2(*(const unsigned*)&h01, *(const unsigned*)&h23);
        *(uint2*)&outz[(size_t)(cbase + c_loc) * R + rbase + 4 * y] = packed;
    }
}

// ---------------- fp16 -> fp32 transpose: in[R][C] f16 -> out[C][R] f32 (y path) ----
__global__ void transpose_f16f32_kernel(const __half* __restrict__ in, float* __restrict__ out,
                                        int R, int C) {
    __shared__ float t[32 * TTW];
    const size_t zoff = (size_t)blockIdx.z * (size_t)R * (size_t)C;
    const int cbase = blockIdx.x * 128;
    const int rbase = blockIdx.y * 32;
    const int x = threadIdx.x, y = threadIdx.y;

    const __half* __restrict__ inz = in + zoff;
#pragma unroll
    for (int it = 0; it < 4; it++) {
        const int r = y + 8 * it;
        uint2 raw = *(const uint2*)&inz[(size_t)(rbase + r) * C + cbase + 4 * x];
        float2 f01 = __half22float2(*(const __half2*)&raw.x);
        float2 f23 = __half22float2(*(const __half2*)&raw.y);
        *(float4*)&t[r * TTW + 4 * x] = make_float4(f01.x, f01.y, f23.x, f23.y);
    }
    __syncthreads();

    float* __restrict__ outz = out + zoff;
#pragma unroll
    for (int it = 0; it < 4; it++) {
        const int c_loc = x + 32 * it;
        float4 v;
        v.x = t[(4 * y + 0) * TTW + c_loc];
        v.y = t[(4 * y + 1) * TTW + c_loc];
        v.z = t[(4 * y + 2) * TTW + c_loc];
        v.w = t[(4 * y + 3) * TTW + c_loc];
        *(float4*)&outz[(size_t)(cbase + c_loc) * R + rbase + 4 * y] = v;
    }
}

// ---------------- fused first fwd stage (14+12), fp16 rows, zero upper half ----------
// NOTE: caller must __syncthreads() before this (it writes sd with no leading barrier).
__device__ __forceinline__ void stageA_fwd_f16(const __half* __restrict__ row0,
                                               const __half* __restrict__ row1,
                                               float2* sd, int tid) {
    float2 v[4][4];
    const int pb = tid + (tid >> 4);
#pragma unroll
    for (int r = 0; r < 4; r++) {
        const int i0 = tid + r * 1024;
        const int i1 = i0 + 4096;
        float2 a0 = make_float2(__half2float(row0[i0]), __half2float(row1[i0]));
        float2 a1 = make_float2(__half2float(row0[i1]), __half2float(row1[i1]));
        float2 X0 = cadd(a0, a1);
        float2 X2 = csub(a0, a1);
        float2 X1 = make_float2(a0.x + a1.y, a0.y - a1.x);
        float2 X3 = make_float2(a0.x - a1.y, a0.y + a1.x);
        float2 w  = g_tw[tid + r * 1024];
        float2 w2 = cmul(w, w);
        float2 w3 = cmul(w2, w);
        v[r][0] = X0;
        v[r][1] = cmul(X1, w);
        v[r][2] = cmul(X2, w2);
        v[r][3] = cmul(X3, w3);
    }
    {
        float2 wb  = g_tw[4 * tid];
        float2 wb2 = cmul(wb, wb);
        float2 wb3 = cmul(wb2, wb);
#pragma unroll
        for (int s = 0; s < 4; s++) {
            bf4_dif(v[0][s], v[1][s], v[2][s], v[3][s]);
            v[1][s] = cmul(v[1][s], wb);
            v[2][s] = cmul(v[2][s], wb2);
            v[3][s] = cmul(v[3][s], wb3);
        }
    }
#pragma unroll
    for (int r = 0; r < 4; r++)
#pragma unroll
        for (int s = 0; s < 4; s++) {
            const int off = r * 1024 + s * 4096;
            sd[pb + off + (off >> 4)] = v[r][s];
        }
}

// ---------------- combined DIF stages (LS, LS-2), smem in/out ----------------
template<int LS>
__device__ __forceinline__ void dif_pair(float2* sd, int tid) {
    constexpr int Q2 = 1 << (LS - 4);
    constexpr int Q  = 1 << (LS - 2);
    constexpr int S  = 1 << (14 - LS);
    __syncthreads();
    const int j2 = tid & (Q2 - 1);
    const int g  = tid >> (LS - 4);
    const int base = (g << LS) + j2;
    const int pb = base + (base >> 4);
    float2 v[4][4];
#pragma unroll
    for (int r = 0; r < 4; r++)
#pragma unroll
        for (int s = 0; s < 4; s++) {
            const int off = r * Q2 + s * Q;
            v[r][s] = sd[pb + off + (off >> 4)];
        }
#pragma unroll
    for (int r = 0; r < 4; r++) {
        bf4_dif(v[r][0], v[r][1], v[r][2], v[r][3]);
        float2 w  = g_tw[(j2 + r * Q2) * S];
        float2 w2 = cmul(w, w);
        float2 w3 = cmul(w2, w);
        v[r][1] = cmul(v[r][1], w);
        v[r][2] = cmul(v[r][2], w2);
        v[r][3] = cmul(v[r][3], w3);
    }
    {
        float2 wb  = g_tw[j2 * (4 * S)];
        float2 wb2 = cmul(wb, wb);
        float2 wb3 = cmul(wb2, wb);
#pragma unroll
        for (int s = 0; s < 4; s++) {
            bf4_dif(v[0][s], v[1][s], v[2][s], v[3][s]);
            v[1][s] = cmul(v[1][s], wb);
            v[2][s] = cmul(v[2][s], wb2);
            v[3][s] = cmul(v[3][s], wb3);
        }
    }
#pragma unroll
    for (int r = 0; r < 4; r++)
#pragma unroll
        for (int s = 0; s < 4; s++) {
            const int off = r * Q2 + s * Q;
            sd[pb + off + (off >> 4)] = v[r][s];
        }
}

// final DIF stage ls=2, sd in -> zh (fp16 packed spectrum, slot order) out
__device__ __forceinline__ void dif_last_to_zh(float2* sd, __half2* zh, int tid) {
    __syncthreads();
#pragma unroll
    for (int tt = 0; tt < (NFFT / 4) / TPB; ++tt) {
        int t = tid + tt * TPB;
        int pb = 4 * t + (t >> 2);
        float2 a0 = sd[pb + 0];
        float2 a1 = sd[pb + 1];
        float2 a2 = sd[pb + 2];
        float2 a3 = sd[pb + 3];
        bf4_dif(a0, a1, a2, a3);
        zh[4 * t + 0] = __floats2half2_rn(a0.x, a0.y);
        zh[4 * t + 1] = __floats2half2_rn(a1.x, a1.y);
        zh[4 * t + 2] = __floats2half2_rn(a2.x, a2.y);
        zh[4 * t + 3] = __floats2half2_rn(a3.x, a3.y);
    }
}

// combined DIT stages (LSA, LSA+2), smem in/out
template<int LSA>
__device__ __forceinline__ void dit_pair(float2* sd, int tid) {
    constexpr int QA   = 1 << (LSA - 2);
    constexpr int SA   = 1 << (14 - LSA);
    constexpr int QB   = 1 << LSA;
    constexpr int SB   = SA >> 2;
    constexpr int LENB = 1 << (LSA + 2);
    __syncthreads();
    const int j = tid & (QA - 1);
    const int G = tid >> (LSA - 2);
    const int base = G * LENB + j;
    const int pb = base + (base >> 4);
    float2 v[4][4];
#pragma unroll
    for (int r = 0; r < 4; r++)
#pragma unroll
        for (int s = 0; s < 4; s++) {
            const int off = r * QA + s * QB;
            v[r][s] = sd[pb + off + (off >> 4)];
        }
    {
        float2 w   = g_tw[j * SA];
        float2 wc  = make_float2(w.x, -w.y);
        float2 wc2 = cmul(wc, wc);
        float2 wc3 = cmul(wc2, wc);
#pragma unroll
        for (int s = 0; s < 4; s++) {
            v[1][s] = cmul(v[1][s], wc);
            v[2][s] = cmul(v[2][s], wc2);
            v[3][s] = cmul(v[3][s], wc3);
            bf4_dit(v[0][s], v[1][s], v[2][s], v[3][s]);
        }
    }
#pragma unroll
    for (int r = 0; r < 4; r++) {
        float2 w   = g_tw[(j + r * QA) * SB];
        float2 wc  = make_float2(w.x, -w.y);
        float2 wc2 = cmul(wc, wc);
        float2 wc3 = cmul(wc2, wc);
        v[r][1] = cmul(v[r][1], wc);
        v[r][2] = cmul(v[r][2], wc2);
        v[r][3] = cmul(v[r][3], wc3);
        bf4_dit(v[r][0], v[r][1], v[r][2], v[r][3]);
    }
#pragma unroll
    for (int r = 0; r < 4; r++)
#pragma unroll
        for (int s = 0; s < 4; s++) {
            const int off = r * QA + s * QB;
            sd[pb + off + (off >> 4)] = v[r][s];
        }
}

// ---------------- fused kernel: h-FFT in smem + 2 channels (batches packed) ----------
__global__ __launch_bounds__(TPB, 1)
void convh2_kernel(const float* __restrict__ bias) {
    extern __shared__ char smraw[];
    float2*  sd = (float2*)smraw;
    __half2* zh = (__half2*)(smraw + NPAD * sizeof(float2));
    const int tid = threadIdx.x;
    const int d0  = 2 * blockIdx.x;

    // ---- phase 1: H spectrum FFT(h_d0 + i*h_d1) -> zh (fp16 packed, slot order) ----
    stageA_fwd_f16(g_hth + (size_t)d0 * L, g_hth + (size_t)(d0 + 1) * L, sd, tid);
    dif_pair<10>(sd, tid);
    dif_pair<6>(sd, tid);
    dif_last_to_zh(sd, zh, tid);

    const float invN = 1.0f / (float)NFFT;

    // ---- phase 2: per channel, r12-style conv with batches packed re/im ----
#pragma unroll 1
    for (int cc = 0; cc < 2; cc++) {
        const int d = d0 + cc;
        const __half* __restrict__ xr0 = g_xt + (size_t)d * L;            // batch 0
        const __half* __restrict__ xr1 = g_xt + (size_t)(D + d) * L;      // batch 1

        __syncthreads();                      // prior pass's sd reads must finish
        stageA_fwd_f16(xr0, xr1, sd, tid);
        dif_pair<10>(sd, tid);
        dif_pair<6>(sd, tid);

        // fused middle: dif_last + slot-local multiply by H_d + dit_first
        // H_d split on the fly from packed zh: needs zh[k] and zh[qperm(k)].
        __syncthreads();
#pragma unroll
        for (int tt = 0; tt < (NFFT / 4) / TPB; ++tt) {
            int t = tid + tt * TPB;
            int pb = 4 * t + (t >> 2);
            float2 a0 = sd[pb + 0];
            float2 a1 = sd[pb + 1];
            float2 a2 = sd[pb + 2];
            float2 a3 = sd[pb + 3];
            bf4_dif(a0, a1, a2, a3);
            float2 Hv[4];
#pragma unroll
            for (int j = 0; j < 4; j++) {
                int k = 4 * t + j;
                int q = qperm(k);
                float2 Hp = __half22float2(zh[k]);
                float2 Hq = __half22float2(zh[q]);
                float2 H0 = make_float2(0.5f * (Hp.x + Hq.x), 0.5f * (Hp.y - Hq.y));
                float2 H1 = make_float2(0.5f * (Hp.y + Hq.y), 0.5f * (Hq.x - Hp.x));
                Hv[j] = cc ? H1 : H0;
            }
            a0 = cmul(a0, Hv[0]);
            a1 = cmul(a1, Hv[1]);
            a2 = cmul(a2, Hv[2]);
            a3 = cmul(a3, Hv[3]);
            bf4_dit(a0, a1, a2, a3);
            sd[pb + 0] = a0;
            sd[pb + 1] = a1;
            sd[pb + 2] = a2;
            sd[pb + 3] = a3;
        }

        dit_pair<4>(sd, tid);
        dit_pair<8>(sd, tid);

        // fused final inverse stage (12+14): smem -> regs -> gmem fp16 (idx < L only)
        __syncthreads();
        {
            const int pb = tid + (tid >> 4);
            float2 v[4][4];
#pragma unroll
            for (int r = 0; r < 4; r++)
#pragma unroll
                for (int s = 0; s < 4; s++) {
                    const int off = r * 1024 + s * 4096;
                    v[r][s] = sd[pb + off + (off >> 4)];
                }
            {
                float2 w   = g_tw[4 * tid];
                float2 wc  = make_float2(w.x, -w.y);
                float2 wc2 = cmul(wc, wc);
                float2 wc3 = cmul(wc2, wc);
#pragma unroll
                for (int s = 0; s < 4; s++) {
                    v[1][s] = cmul(v[1][s], wc);
                    v[2][s] = cmul(v[2][s], wc2);
                    v[3][s] = cmul(v[3][s], wc3);
                    bf4_dit(v[0][s], v[1][s], v[2][s], v[3][s]);
                }
            }
            const float bd = bias[d];
            __half* __restrict__ y0 = g_yt + (size_t)d * L;
            __half* __restrict__ y1 = g_yt + (size_t)(D + d) * L;
#pragma unroll
            for (int r = 0; r < 4; r++) {
                float2 w   = g_tw[tid + r * 1024];
                float2 wc  = make_float2(w.x, -w.y);
                float2 wc2 = cmul(wc, wc);
                float2 wc3 = cmul(wc2, wc);
                v[r][1] = cmul(v[r][1], wc);
                v[r][2] = cmul(v[r][2], wc2);
                v[r][3] = cmul(v[r][3], wc3);
                bf4_dit(v[r][0], v[r][1], v[r][2], v[r][3]);
#pragma unroll
                for (int s = 0; s < 2; s++) {
                    const int idx = tid + r * 1024 + s * 4096;
                    y0[idx] = __float2half_rn(fmaf(v[r][s].x, invN, bd));
                    y1[idx] = __float2half_rn(fmaf(v[r][s].y, invN, bd));
                }
            }
        }
    }
}

// ---------------- launch ----------------
extern "C" void kernel_launch(void* const* d_in, const int* in_sizes, int n_in,
                              void* d_out, int out_size) {
    const float* x    = (const float*)d_in[0];
    const float* h    = (const float*)d_in[1];
    const float* bias = (const float*)d_in[2];
    float* out = (float*)d_out;

    void *xt_p, *hth_p, *yt_p;
    cudaGetSymbolAddress(&xt_p,  g_xt);
    cudaGetSymbolAddress(&hth_p, g_hth);
    cudaGetSymbolAddress(&yt_p,  g_yt);

    cudaFuncSetAttribute(convh2_kernel, cudaFuncAttributeMaxDynamicSharedMemorySize, SMEM_CONVH);

    init_kernel<<<8, 512>>>();
    // x: [L][D] fp32 per batch -> [D][L] fp16
    transpose_f32f16_kernel<<<dim3(D / 128, L / 32, B), dim3(32, 8)>>>(x, (__half*)xt_p, L, D);
    // h: [L][D] fp32 -> [D][L] fp16
    transpose_f32f16_kernel<<<dim3(D / 128, L / 32, 1), dim3(32, 8)>>>(h, (__half*)hth_p, L, D);
    // fused: h-FFT in smem + 2 channels x (2 batches packed) per block
    convh2_kernel<<<D / 2, TPB, SMEM_CONVH>>>(bias);
    // y: [D][L] fp16 per batch -> [L][D] fp32
    transpose_f16f32_kernel<<<dim3(L / 128, D / 32, B), dim3(32, 8)>>>((const __half*)yt_p, out, D, L);
}

// round 15
// speedup vs baseline: 1.0550x; 1.0218x over previous
#include <cuda_runtime.h>
#include <cuda_fp16.h>
#include <cstdint>

// Problem constants
#define B  2
#define L  8192
#define D  1024
#define NFFT 16384
#define TPB 1024
#define NTW (NFFT / 4)                        // 4096 twiddle quads = 64 KB
#define NPAD (NFFT + NFFT/16)
#define SMEM_BYTES (NPAD * sizeof(float2))    // 139264 B

// ---------------- device scratch ----------------
__device__ __half  g_xt[(size_t)B * D * L];   // x transposed [B][D][L], fp16
__device__ __half  g_hth[(size_t)D * L];      // h transposed [D][L], fp16
__device__ __half2 g_hfh[(size_t)D * NFFT];   // H spectrum, fp16 complex (digit-reversed)
__device__ __half  g_yt[(size_t)B * D * L];   // y transposed [B][D][L], fp16
__device__ float4  g_tw4[NTW];                // {cos k, sin k, cos 2k, sin 2k}

// ---------------- helpers ----------------
__device__ __forceinline__ int pidx(int a) { return a + (a >> 4); }

__device__ __forceinline__ float2 cmul(float2 a, float2 b) {
    return make_float2(fmaf(a.x, b.x, -a.y * b.y),
                       fmaf(a.x, b.y,  a.y * b.x));
}
__device__ __forceinline__ float2 cadd(float2 a, float2 b) { return make_float2(a.x + b.x, a.y + b.y); }
__device__ __forceinline__ float2 csub(float2 a, float2 b) { return make_float2(a.x - b.x, a.y - b.y); }

__device__ __forceinline__ void bf4_dif(float2& a0, float2& a1, float2& a2, float2& a3) {
    float2 t0 = cadd(a0, a2), t1 = csub(a0, a2);
    float2 t2 = cadd(a1, a3), t3 = csub(a1, a3);
    a0 = cadd(t0, t2);
    a2 = csub(t0, t2);
    a1 = make_float2(t1.x + t3.y, t1.y - t3.x);  // t1 - i*t3
    a3 = make_float2(t1.x - t3.y, t1.y + t3.x);  // t1 + i*t3
}
__device__ __forceinline__ void bf4_dit(float2& a0, float2& a1, float2& a2, float2& a3) {
    float2 t0 = cadd(a0, a2), t1 = csub(a0, a2);
    float2 t2 = cadd(a1, a3), t3 = csub(a1, a3);
    a0 = cadd(t0, t2);
    a2 = csub(t0, t2);
    a1 = make_float2(t1.x - t3.y, t1.y + t3.x);  // t1 + i*t3
    a3 = make_float2(t1.x + t3.y, t1.y - t3.x);  // t1 - i*t3
}

// base-4 digit reversal of 14 bits: bit-reverse then swap adjacent bit pairs
__device__ __forceinline__ int rev4_14(int x) {
    unsigned y = __brev((unsigned)x) >> 18;
    return (int)(((y & 0x2AAAu) >> 1) | ((y & 0x1555u) << 1));
}

// ---------------- init: twiddle quads {W^k, W^2k} ----------------
__global__ void init_kernel() {
    int k = blockIdx.x * blockDim.x + threadIdx.x;
    if (k < NTW) {
        float s1, c1, s2, c2;
        sincospif(-2.0f * (float)k / (float)NFFT, &s1, &c1);
        sincospif(-4.0f * (float)k / (float)NFFT, &s2, &c2);
        g_tw4[k] = make_float4(c1, s1, c2, s2);
    }
}

#define TTW 132   // padded tile row width in floats (128 + 4)

// ---------------- fp32 -> fp16 transpose: in[R][C] f32 -> out[C][R] f16 ----------------
__global__ void transpose_f32f16_kernel(const float* __restrict__ in, __half* __restrict__ out,
                                        int R, int C) {
    __shared__ float t[32 * TTW];
    const size_t zoff = (size_t)blockIdx.z * (size_t)R * (size_t)C;
    const int cbase = blockIdx.x * 128;
    const int rbase = blockIdx.y * 32;
    const int x = threadIdx.x, y = threadIdx.y;

    const float4* __restrict__ in4 = (const float4*)(in + zoff);
#pragma unroll
    for (int it = 0; it < 4; it++) {
        const int r = y + 8 * it;
        float4 v = in4[((size_t)(rbase + r) * C + cbase) / 4 + x];
        *(float4*)&t[r * TTW + 4 * x] = v;
    }
    __syncthreads();

    __half* __restrict__ outz = out + zoff;
#pragma unroll
    for (int it = 0; it < 4; it++) {
        const int c_loc = x + 32 * it;
        __half2 h01 = __floats2half2_rn(t[(4 * y + 0) * TTW + c_loc],
                                        t[(4 * y + 1) * TTW + c_loc]);
        __half2 h23 = __floats2half2_rn(t[(4 * y + 2) * TTW + c_loc],
                                        t[(4 * y + 3) * TTW + c_loc]);
        uint2 packed = make_uint2(*(const unsigned*)&h01, *(const unsigned*)&h23);
        *(uint2*)&outz[(size_t)(cbase + c_loc) * R + rbase + 4 * y] = packed;
    }
}

// ---------------- fp16 -> fp32 transpose: in[R][C] f16 -> out[C][R] f32 (y path) ----
__global__ void transpose_f16f32_kernel(const __half* __restrict__ in, float* __restrict__ out,
                                        int R, int C) {
    __shared__ float t[32 * TTW];
    const size_t zoff = (size_t)blockIdx.z * (size_t)R * (size_t)C;
    const int cbase = blockIdx.x * 128;
    const int rbase = blockIdx.y * 32;
    const int x = threadIdx.x, y = threadIdx.y;

    const __half* __restrict__ inz = in + zoff;
#pragma unroll
    for (int it = 0; it < 4; it++) {
        const int r = y + 8 * it;
        uint2 raw = *(const uint2*)&inz[(size_t)(rbase + r) * C + cbase + 4 * x];
        float2 f01 = __half22float2(*(const __half2*)&raw.x);
        float2 f23 = __half22float2(*(const __half2*)&raw.y);
        *(float4*)&t[r * TTW + 4 * x] = make_float4(f01.x, f01.y, f23.x, f23.y);
    }
    __syncthreads();

    float* __restrict__ outz = out + zoff;
#pragma unroll
    for (int it = 0; it < 4; it++) {
        const int c_loc = x + 32 * it;
        float4 v;
        v.x = t[(4 * y + 0) * TTW + c_loc];
        v.y = t[(4 * y + 1) * TTW + c_loc];
        v.z = t[(4 * y + 2) * TTW + c_loc];
        v.w = t[(4 * y + 3) * TTW + c_loc];
        *(float4*)&outz[(size_t)(cbase + c_loc) * R + rbase + 4 * y] = v;
    }
}

// ---------------- fused first fwd stage (14+12), fp16 rows, zero upper half ----------
__device__ __forceinline__ void stageA_fwd_f16(const __half* __restrict__ row0,
                                               const __half* __restrict__ row1,
                                               float2* sd, int tid) {
    float2 v[4][4];
    const int pb = tid + (tid >> 4);
#pragma unroll
    for (int r = 0; r < 4; r++) {
        const int i0 = tid + r * 1024;
        const int i1 = i0 + 4096;
        float2 a0 = make_float2(__half2float(row0[i0]), __half2float(row1[i0]));
        float2 a1 = make_float2(__half2float(row0[i1]), __half2float(row1[i1]));
        float2 X0 = cadd(a0, a1);
        float2 X2 = csub(a0, a1);
        float2 X1 = make_float2(a0.x + a1.y, a0.y - a1.x);
        float2 X3 = make_float2(a0.x - a1.y, a0.y + a1.x);
        float4 t4 = g_tw4[tid + r * 1024];
        float2 w  = make_float2(t4.x, t4.y);
        float2 w2 = make_float2(t4.z, t4.w);
        float2 w3 = cmul(w, w2);
        v[r][0] = X0;
        v[r][1] = cmul(X1, w);
        v[r][2] = cmul(X2, w2);
        v[r][3] = cmul(X3, w3);
    }
    {
        float4 t4 = g_tw4[4 * tid];
        float2 wb  = make_float2(t4.x, t4.y);
        float2 wb2 = make_float2(t4.z, t4.w);
        float2 wb3 = cmul(wb, wb2);
#pragma unroll
        for (int s = 0; s < 4; s++) {
            bf4_dif(v[0][s], v[1][s], v[2][s], v[3][s]);
            v[1][s] = cmul(v[1][s], wb);
            v[2][s] = cmul(v[2][s], wb2);
            v[3][s] = cmul(v[3][s], wb3);
        }
    }
#pragma unroll
    for (int r = 0; r < 4; r++)
#pragma unroll
        for (int s = 0; s < 4; s++) {
            const int off = r * 1024 + s * 4096;
            sd[pb + off + (off >> 4)] = v[r][s];
        }
}

// ---------------- combined DIF stages (LS, LS-2), smem in/out ----------------
template<int LS>
__device__ __forceinline__ void dif_pair(float2* sd, int tid) {
    constexpr int Q2 = 1 << (LS - 4);
    constexpr int Q  = 1 << (LS - 2);
    constexpr int S  = 1 << (14 - LS);
    __syncthreads();
    const int j2 = tid & (Q2 - 1);
    const int g  = tid >> (LS - 4);
    const int base = (g << LS) + j2;
    const int pb = base + (base >> 4);
    float2 v[4][4];
#pragma unroll
    for (int r = 0; r < 4; r++)
#pragma unroll
        for (int s = 0; s < 4; s++) {
            const int off = r * Q2 + s * Q;
            v[r][s] = sd[pb + off + (off >> 4)];
        }
#pragma unroll
    for (int r = 0; r < 4; r++) {
        bf4_dif(v[r][0], v[r][1], v[r][2], v[r][3]);
        float4 t4 = g_tw4[(j2 + r * Q2) * S];
        float2 w  = make_float2(t4.x, t4.y);
        float2 w2 = make_float2(t4.z, t4.w);
        float2 w3 = cmul(w, w2);
        v[r][1] = cmul(v[r][1], w);
        v[r][2] = cmul(v[r][2], w2);
        v[r][3] = cmul(v[r][3], w3);
    }
    {
        float4 t4 = g_tw4[j2 * (4 * S)];
        float2 wb  = make_float2(t4.x, t4.y);
        float2 wb2 = make_float2(t4.z, t4.w);
        float2 wb3 = cmul(wb, wb2);
#pragma unroll
        for (int s = 0; s < 4; s++) {
            bf4_dif(v[0][s], v[1][s], v[2][s], v[3][s]);
            v[1][s] = cmul(v[1][s], wb);
            v[2][s] = cmul(v[2][s], wb2);
            v[3][s] = cmul(v[3][s], wb3);
        }
    }
#pragma unroll
    for (int r = 0; r < 4; r++)
#pragma unroll
        for (int s = 0; s < 4; s++) {
            const int off = r * Q2 + s * Q;
            sd[pb + off + (off >> 4)] = v[r][s];
        }
}

// final DIF stage ls=2 (hfft only)
__device__ __forceinline__ void dif_last(float2* sd, int tid) {
    __syncthreads();
#pragma unroll
    for (int tt = 0; tt < (NFFT / 4) / TPB; ++tt) {
        int t = tid + tt * TPB;
        int pb = 4 * t + (t >> 2);
        float2 a0 = sd[pb + 0];
        float2 a1 = sd[pb + 1];
        float2 a2 = sd[pb + 2];
        float2 a3 = sd[pb + 3];
        bf4_dif(a0, a1, a2, a3);
        sd[pb + 0] = a0;
        sd[pb + 1] = a1;
        sd[pb + 2] = a2;
        sd[pb + 3] = a3;
    }
}

// combined DIT stages (LSA, LSA+2), smem in/out
template<int LSA>
__device__ __forceinline__ void dit_pair(float2* sd, int tid) {
    constexpr int QA   = 1 << (LSA - 2);
    constexpr int SA   = 1 << (14 - LSA);
    constexpr int QB   = 1 << LSA;
    constexpr int SB   = SA >> 2;
    constexpr int LENB = 1 << (LSA + 2);
    __syncthreads();
    const int j = tid & (QA - 1);
    const int G = tid >> (LSA - 2);
    const int base = G * LENB + j;
    const int pb = base + (base >> 4);
    float2 v[4][4];
#pragma unroll
    for (int r = 0; r < 4; r++)
#pragma unroll
        for (int s = 0; s < 4; s++) {
            const int off = r * QA + s * QB;
            v[r][s] = sd[pb + off + (off >> 4)];
        }
    {
        float4 t4 = g_tw4[j * SA];
        float2 wc  = make_float2(t4.x, -t4.y);
        float2 wc2 = make_float2(t4.z, -t4.w);
        float2 wc3 = cmul(wc, wc2);
#pragma unroll
        for (int s = 0; s < 4; s++) {
            v[1][s] = cmul(v[1][s], wc);
            v[2][s] = cmul(v[2][s], wc2);
            v[3][s] = cmul(v[3][s], wc3);
            bf4_dit(v[0][s], v[1][s], v[2][s], v[3][s]);
        }
    }
#pragma unroll
    for (int r = 0; r < 4; r++) {
        float4 t4 = g_tw4[(j + r * QA) * SB];
        float2 wc  = make_float2(t4.x, -t4.y);
        float2 wc2 = make_float2(t4.z, -t4.w);
        float2 wc3 = cmul(wc, wc2);
        v[r][1] = cmul(v[r][1], wc);
        v[r][2] = cmul(v[r][2], wc2);
        v[r][3] = cmul(v[r][3], wc3);
        bf4_dit(v[r][0], v[r][1], v[r][2], v[r][3]);
    }
#pragma unroll
    for (int r = 0; r < 4; r++)
#pragma unroll
        for (int s = 0; s < 4; s++) {
            const int off = r * QA + s * QB;
            sd[pb + off + (off >> 4)] = v[r][s];
        }
}

// ---------------- H spectra: TWO channels per block via Hermitian split, fp16 out ----
__global__ __launch_bounds__(TPB, 1)
void hfft_kernel() {
    extern __shared__ float2 sd[];
    const int tid = threadIdx.x;
    const int d0  = 2 * blockIdx.x;
    const int d1  = d0 + 1;

    stageA_fwd_f16(g_hth + (size_t)d0 * L, g_hth + (size_t)d1 * L, sd, tid);
    dif_pair<10>(sd, tid);
    dif_pair<6>(sd, tid);
    dif_last(sd, tid);
    __syncthreads();

    __half2* __restrict__ hf0 = g_hfh + (size_t)d0 * NFFT;
    __half2* __restrict__ hf1 = g_hfh + (size_t)d1 * NFFT;
#pragma unroll
    for (int tt = 0; tt < NFFT / TPB; ++tt) {
        int p = tid + tt * TPB;
        int q = rev4_14((NFFT - rev4_14(p)) & (NFFT - 1));
        float2 zp = sd[p + (p >> 4)];
        float2 zq = sd[q + (q >> 4)];
        // H0 = (zp + conj(zq))/2 ; H1 = -i*(zp - conj(zq))/2
        hf0[p] = __floats2half2_rn(0.5f * (zp.x + zq.x), 0.5f * (zp.y - zq.y));
        hf1[p] = __floats2half2_rn(0.5f * (zp.y + zq.y), 0.5f * (zq.x - zp.x));
    }
}

// ---------------- conv: one channel per block, both batches packed re/im ----------------
__global__ __launch_bounds__(TPB, 1)
void conv_kernel(const float* __restrict__ bias) {
    extern __shared__ float2 sd[];
    const int tid = threadIdx.x;
    const int d   = blockIdx.x;

    // fwd: fused first stage from gmem (fp16 x), then two smem pair-stages
    stageA_fwd_f16(g_xt + (size_t)d * L, g_xt + (size_t)(D + d) * L, sd, tid);
    dif_pair<10>(sd, tid);
    dif_pair<6>(sd, tid);

    // fused: dif_last + pointwise *H (fp16) + dit_first  (all on slots 4t..4t+3)
    __syncthreads();
    const __half2* __restrict__ hfh = g_hfh + (size_t)d * NFFT;
#pragma unroll
    for (int tt = 0; tt < (NFFT / 4) / TPB; ++tt) {
        int t = tid + tt * TPB;
        int pb = 4 * t + (t >> 2);
        float2 a0 = sd[pb + 0];
        float2 a1 = sd[pb + 1];
        float2 a2 = sd[pb + 2];
        float2 a3 = sd[pb + 3];
        bf4_dif(a0, a1, a2, a3);
        uint4 raw = __ldcs((const uint4*)(hfh + 4 * t));
        a0 = cmul(a0, __half22float2(*(const __half2*)&raw.x));
        a1 = cmul(a1, __half22float2(*(const __half2*)&raw.y));
        a2 = cmul(a2, __half22float2(*(const __half2*)&raw.z));
        a3 = cmul(a3, __half22float2(*(const __half2*)&raw.w));
        bf4_dit(a0, a1, a2, a3);
        sd[pb + 0] = a0;
        sd[pb + 1] = a1;
        sd[pb + 2] = a2;
        sd[pb + 3] = a3;
    }

    dit_pair<4>(sd, tid);
    dit_pair<8>(sd, tid);

    // fused final inverse stage (12+14): smem -> regs -> gmem fp16 (idx < L only)
    __syncthreads();
    {
        const int pb = tid + (tid >> 4);
        float2 v[4][4];
#pragma unroll
        for (int r = 0; r < 4; r++)
#pragma unroll
            for (int s = 0; s < 4; s++) {
                const int off = r * 1024 + s * 4096;
                v[r][s] = sd[pb + off + (off >> 4)];
            }
        // level A = stage 12: conj twiddles idx 4*tid
        {
            float4 t4 = g_tw4[4 * tid];
            float2 wc  = make_float2(t4.x, -t4.y);
            float2 wc2 = make_float2(t4.z, -t4.w);
            float2 wc3 = cmul(wc, wc2);
#pragma unroll
            for (int s = 0; s < 4; s++) {
                v[1][s] = cmul(v[1][s], wc);
                v[2][s] = cmul(v[2][s], wc2);
                v[3][s] = cmul(v[3][s], wc3);
                bf4_dit(v[0][s], v[1][s], v[2][s], v[3][s]);
            }
        }
        // level B = stage 14: conj twiddles idx tid + r*1024
        const float invN = 1.0f / (float)NFFT;
        const float bd = bias[d];
        __half* __restrict__ y0 = g_yt + (size_t)d * L;
        __half* __restrict__ y1 = g_yt + (size_t)(D + d) * L;
#pragma unroll
        for (int r = 0; r < 4; r++) {
            float4 t4 = g_tw4[tid + r * 1024];
            float2 wc  = make_float2(t4.x, -t4.y);
            float2 wc2 = make_float2(t4.z, -t4.w);
            float2 wc3 = cmul(wc, wc2);
            v[r][1] = cmul(v[r][1], wc);
            v[r][2] = cmul(v[r][2], wc2);
            v[r][3] = cmul(v[r][3], wc3);
            bf4_dit(v[r][0], v[r][1], v[r][2], v[r][3]);
#pragma unroll
            for (int s = 0; s < 2; s++) {
                const int idx = tid + r * 1024 + s * 4096;
                y0[idx] = __float2half_rn(fmaf(v[r][s].x, invN, bd));
                y1[idx] = __float2half_rn(fmaf(v[r][s].y, invN, bd));
            }
        }
    }
}

// ---------------- launch ----------------
extern "C" void kernel_launch(void* const* d_in, const int* in_sizes, int n_in,
                              void* d_out, int out_size) {
    const float* x    = (const float*)d_in[0];
    const float* h    = (const float*)d_in[1];
    const float* bias = (const float*)d_in[2];
    float* out = (float*)d_out;

    void *xt_p, *hth_p, *yt_p;
    cudaGetSymbolAddress(&xt_p,  g_xt);
    cudaGetSymbolAddress(&hth_p, g_hth);
    cudaGetSymbolAddress(&yt_p,  g_yt);

    cudaFuncSetAttribute(hfft_kernel, cudaFuncAttributeMaxDynamicSharedMemorySize, SMEM_BYTES);
    cudaFuncSetAttribute(conv_kernel, cudaFuncAttributeMaxDynamicSharedMemorySize, SMEM_BYTES);

    init_kernel<<<8, 512>>>();
    // x: [L][D] fp32 per batch -> [D][L] fp16
    transpose_f32f16_kernel<<<dim3(D / 128, L / 32, B), dim3(32, 8)>>>(x, (__half*)xt_p, L, D);
    // h: [L][D] fp32 -> [D][L] fp16
    transpose_f32f16_kernel<<<dim3(D / 128, L / 32, 1), dim3(32, 8)>>>(h, (__half*)hth_p, L, D);
    hfft_kernel<<<D / 2, TPB, SMEM_BYTES>>>();
    conv_kernel<<<D, TPB, SMEM_BYTES>>>(bias);
    // y: [D][L] fp16 per batch -> [L][D] fp32
    transpose_f16f32_kernel<<<dim3(L / 128, D / 32, B), dim3(32, 8)>>>((const __half*)yt_p, out, D, L);
}